// round 1
// baseline (speedup 1.0000x reference)
#include <cuda_runtime.h>
#include <cuda_bf16.h>
#include <math.h>

// Problem constants (fixed by the dataset)
#define NN 100000
#define EE 1000000
#define DD 128      // D_IN == D_OUT
#define KK 256      // concatenated K = 2*D

// Scratch: X[node][0:128] = A (sum of h_src * n_s*n_d, init ego),
//          X[node][128:256] = B (sum of (h_src*h_dst) * n_s*n_d, init 0)
__device__ float g_X[(size_t)NN * KK];

// ---------------------------------------------------------------------------
// Kernel 1: init X
// ---------------------------------------------------------------------------
__global__ void init_kernel(const float4* __restrict__ ego, float4* __restrict__ X)
{
    int tid = blockIdx.x * blockDim.x + threadIdx.x;   // over N*64 float4
    const int total = NN * 64;                          // 256 floats/row = 64 float4
    if (tid >= total) return;
    int row = tid >> 6;          // /64
    int q   = tid & 63;
    float4 v;
    if (q < 32) {
        v = ego[(size_t)row * 32 + q];
    } else {
        v = make_float4(0.f, 0.f, 0.f, 0.f);
    }
    X[tid] = v;
}

// ---------------------------------------------------------------------------
// Kernel 2: per-edge scatter. One warp per edge.
// ---------------------------------------------------------------------------
__device__ __forceinline__ void red_add_v4(float* p, float4 v)
{
    asm volatile("red.global.add.v4.f32 [%0], {%1, %2, %3, %4};"
                 :: "l"(p), "f"(v.x), "f"(v.y), "f"(v.z), "f"(v.w)
                 : "memory");
}

__global__ void edge_kernel(const float4* __restrict__ ego,
                            const float*  __restrict__ norm,
                            const int*    __restrict__ src,
                            const int*    __restrict__ dst,
                            float*        __restrict__ X)
{
    int gwarp = (blockIdx.x * blockDim.x + threadIdx.x) >> 5;
    int lane  = threadIdx.x & 31;
    if (gwarp >= EE) return;

    int s = __ldg(src + gwarp);
    int d = __ldg(dst + gwarp);
    float w = __ldg(norm + s) * __ldg(norm + d);

    float4 hs = __ldg(ego + (size_t)s * 32 + lane);
    float4 hd = __ldg(ego + (size_t)d * 32 + lane);

    float4 m1 = make_float4(hs.x * w, hs.y * w, hs.z * w, hs.w * w);
    float4 m2 = make_float4(hs.x * hd.x * w, hs.y * hd.y * w,
                            hs.z * hd.z * w, hs.w * hd.w * w);

    float* base = X + (size_t)d * KK + lane * 4;
    red_add_v4(base,       m1);   // A part
    red_add_v4(base + DD,  m2);   // B part
}

// ---------------------------------------------------------------------------
// Kernel 3: C = X @ [W1;W2], then leaky_relu(0.2) + row L2-normalize.
// Block: 64 rows x 128 cols, 256 threads, thread tile 4x8.
// SMEM: Ws[256][128] (128 KB) + Xs[64][64] transposed w/ pad 65 (16.6 KB)
// ---------------------------------------------------------------------------
#define BM 64
#define XS_PITCH 65

__global__ void __launch_bounds__(256, 1)
gemm_epilogue_kernel(const float* __restrict__ W1,
                     const float* __restrict__ W2,
                     float*       __restrict__ out)
{
    extern __shared__ float smem[];
    float* Ws = smem;                 // 256*128 floats
    float* Xs = smem + KK * DD;       // 64 * XS_PITCH floats (k-major, row minor)

    const int tid = threadIdx.x;
    const int tx  = tid & 15;         // col group (8 cols each)
    const int ty  = tid >> 4;         // row group (4 rows each)
    const int tx8 = tx * 8;
    const int ty4 = ty * 4;
    const int rowBase = blockIdx.x * BM;

    // Load W = [W1; W2] into shared, row-major [k][j]
    const float4* W1v = (const float4*)W1;
    const float4* W2v = (const float4*)W2;
    float4* Wsv = (float4*)Ws;
    #pragma unroll
    for (int i = 0; i < 32; ++i) {
        int m = tid + i * 256;        // 0 .. 8191 (float4 index)
        int k  = m >> 5;              // 0..255
        int j4 = m & 31;
        float4 v = (k < DD) ? W1v[(size_t)k * 32 + j4]
                            : W2v[(size_t)(k - DD) * 32 + j4];
        Wsv[m] = v;
    }

    float acc[4][8];
    #pragma unroll
    for (int i = 0; i < 4; ++i)
        #pragma unroll
        for (int j = 0; j < 8; ++j) acc[i][j] = 0.f;

    const float4* X4 = (const float4*)g_X;
    __syncthreads();   // Ws ready

    for (int kc = 0; kc < KK; kc += 64) {
        // Load X tile (64 rows x 64 k), transposed into Xs[k][row]
        #pragma unroll
        for (int i = 0; i < 4; ++i) {
            int l   = tid + i * 256;      // 0..1023
            int r   = l >> 4;             // 0..63
            int kq  = l & 15;             // 0..15 (float4 within k-chunk)
            int grow = rowBase + r;
            if (grow >= NN) grow = NN - 1;
            float4 v = X4[(size_t)grow * 64 + (kc >> 2) + kq];
            int kk = kq * 4;
            Xs[(kk + 0) * XS_PITCH + r] = v.x;
            Xs[(kk + 1) * XS_PITCH + r] = v.y;
            Xs[(kk + 2) * XS_PITCH + r] = v.z;
            Xs[(kk + 3) * XS_PITCH + r] = v.w;
        }
        __syncthreads();

        #pragma unroll 8
        for (int k = 0; k < 64; ++k) {
            float xv[4];
            #pragma unroll
            for (int i = 0; i < 4; ++i) xv[i] = Xs[k * XS_PITCH + ty4 + i];
            const float4 w0 = *(const float4*)&Ws[(kc + k) * DD + tx8];
            const float4 w1 = *(const float4*)&Ws[(kc + k) * DD + tx8 + 4];
            #pragma unroll
            for (int i = 0; i < 4; ++i) {
                acc[i][0] = fmaf(xv[i], w0.x, acc[i][0]);
                acc[i][1] = fmaf(xv[i], w0.y, acc[i][1]);
                acc[i][2] = fmaf(xv[i], w0.z, acc[i][2]);
                acc[i][3] = fmaf(xv[i], w0.w, acc[i][3]);
                acc[i][4] = fmaf(xv[i], w1.x, acc[i][4]);
                acc[i][5] = fmaf(xv[i], w1.y, acc[i][5]);
                acc[i][6] = fmaf(xv[i], w1.z, acc[i][6]);
                acc[i][7] = fmaf(xv[i], w1.w, acc[i][7]);
            }
        }
        __syncthreads();
    }

    // Epilogue: leaky relu + row L2 norm (reduce across the 16 tx threads)
    float* red_ = Xs;   // reuse: needs 64*16 + 64 floats <= 64*65
    #pragma unroll
    for (int i = 0; i < 4; ++i) {
        float p = 0.f;
        #pragma unroll
        for (int j = 0; j < 8; ++j) {
            float v = acc[i][j];
            v = (v >= 0.f) ? v : 0.2f * v;
            acc[i][j] = v;
            p = fmaf(v, v, p);
        }
        red_[(ty4 + i) * 16 + tx] = p;
    }
    __syncthreads();

    if (tid < BM) {
        float s = 0.f;
        #pragma unroll
        for (int t = 0; t < 16; ++t) s += red_[tid * 16 + t];
        red_[BM * 16 + tid] = 1.f / fmaxf(sqrtf(s), 1e-12f);
    }
    __syncthreads();

    float4* out4 = (float4*)out;
    #pragma unroll
    for (int i = 0; i < 4; ++i) {
        int grow = rowBase + ty4 + i;
        if (grow < NN) {
            float iv = red_[BM * 16 + ty4 + i];
            float4 o0 = make_float4(acc[i][0] * iv, acc[i][1] * iv,
                                    acc[i][2] * iv, acc[i][3] * iv);
            float4 o1 = make_float4(acc[i][4] * iv, acc[i][5] * iv,
                                    acc[i][6] * iv, acc[i][7] * iv);
            out4[(size_t)grow * 32 + tx * 2]     = o0;
            out4[(size_t)grow * 32 + tx * 2 + 1] = o1;
        }
    }
}

// ---------------------------------------------------------------------------
// Launch
// ---------------------------------------------------------------------------
extern "C" void kernel_launch(void* const* d_in, const int* in_sizes, int n_in,
                              void* d_out, int out_size)
{
    const float* ego  = (const float*)d_in[0];   // [N,128]
    const float* norm = (const float*)d_in[1];   // [N,1]
    const int*   src  = (const int*)d_in[2];     // [E]
    const int*   dst  = (const int*)d_in[3];     // [E]
    const float* W1   = (const float*)d_in[4];   // [128,128]
    const float* W2   = (const float*)d_in[5];   // [128,128]
    float* out = (float*)d_out;

    float* X;
    cudaGetSymbolAddress((void**)&X, g_X);

    // 1) init X
    {
        int total = NN * 64;
        int thr = 256;
        int blk = (total + thr - 1) / thr;
        init_kernel<<<blk, thr>>>((const float4*)ego, (float4*)X);
    }

    // 2) edge scatter (1 warp per edge)
    {
        int thr = 256;                          // 8 warps/block
        int blk = (EE + 7) / 8;
        edge_kernel<<<blk, thr>>>((const float4*)ego, norm, src, dst, X);
    }

    // 3) GEMM + leaky relu + normalize
    {
        int smem = (KK * DD + BM * XS_PITCH) * (int)sizeof(float);  // ~147 KB
        cudaFuncSetAttribute(gemm_epilogue_kernel,
                             cudaFuncAttributeMaxDynamicSharedMemorySize, smem);
        int blk = (NN + BM - 1) / BM;
        gemm_epilogue_kernel<<<blk, 256, smem>>>(W1, W2, out);
    }
}

// round 2
// speedup vs baseline: 1.3205x; 1.3205x over previous
#include <cuda_runtime.h>
#include <cuda_bf16.h>
#include <math.h>

// Problem constants (fixed by dataset)
#define NN 100000
#define EE 1000000
#define DD 128
#define KK 256

#define SCAN_CHUNK 512
#define NB_SCAN ((NN + SCAN_CHUNK - 1) / SCAN_CHUNK)   // 196

// Scratch
__device__ float g_X[(size_t)NN * KK];     // [N][256]: A | B
__device__ int   g_cnt[NN];
__device__ int   g_off[NN];
__device__ int   g_cur[NN];
__device__ int   g_part[256];
__device__ int2  g_meta[EE];               // {src, w_as_int}

// ---------------------------------------------------------------------------
// CSR build
// ---------------------------------------------------------------------------
__global__ void zero_cnt_kernel(int* __restrict__ cnt)
{
    int i = blockIdx.x * blockDim.x + threadIdx.x;
    if (i < NN) cnt[i] = 0;
}

__global__ void hist_kernel(const int* __restrict__ dst, int* __restrict__ cnt)
{
    int e = blockIdx.x * blockDim.x + threadIdx.x;
    if (e < EE) atomicAdd(&cnt[__ldg(dst + e)], 1);
}

__global__ void scan_local_kernel(const int* __restrict__ cnt,
                                  int* __restrict__ off,
                                  int* __restrict__ part)
{
    __shared__ int sh[SCAN_CHUNK];
    int t   = threadIdx.x;
    int idx = blockIdx.x * SCAN_CHUNK + t;
    int v = (idx < NN) ? cnt[idx] : 0;
    sh[t] = v;
    __syncthreads();
    #pragma unroll
    for (int o = 1; o < SCAN_CHUNK; o <<= 1) {
        int x = (t >= o) ? sh[t - o] : 0;
        __syncthreads();
        sh[t] += x;
        __syncthreads();
    }
    if (idx < NN) off[idx] = sh[t] - v;          // exclusive
    if (t == SCAN_CHUNK - 1) part[blockIdx.x] = sh[t];
}

__global__ void scan_part_kernel(int* __restrict__ part)
{
    __shared__ int sh[256];
    int t = threadIdx.x;
    int v = (t < NB_SCAN) ? part[t] : 0;
    sh[t] = v;
    __syncthreads();
    #pragma unroll
    for (int o = 1; o < 256; o <<= 1) {
        int x = (t >= o) ? sh[t - o] : 0;
        __syncthreads();
        sh[t] += x;
        __syncthreads();
    }
    if (t < NB_SCAN) part[t] = sh[t] - v;        // exclusive
}

__global__ void scan_add_kernel(int* __restrict__ off,
                                int* __restrict__ cur,
                                const int* __restrict__ part)
{
    int idx = blockIdx.x * SCAN_CHUNK + threadIdx.x;
    if (idx < NN) {
        int o = off[idx] + part[blockIdx.x];
        off[idx] = o;
        cur[idx] = o;
    }
}

__global__ void scatter_kernel(const int* __restrict__ src,
                               const int* __restrict__ dst,
                               const float* __restrict__ norm,
                               int* __restrict__ cur,
                               int2* __restrict__ meta)
{
    int e = blockIdx.x * blockDim.x + threadIdx.x;
    if (e >= EE) return;
    int s = __ldg(src + e);
    int d = __ldg(dst + e);
    float w = __ldg(norm + s) * __ldg(norm + d);
    int pos = atomicAdd(&cur[d], 1);
    meta[pos] = make_int2(s, __float_as_int(w));
}

// ---------------------------------------------------------------------------
// Aggregate: one warp per node. A = ego[d] + sum(w*h_src); B = sum(w*h_src*h_dst)
// ---------------------------------------------------------------------------
__global__ void aggregate_kernel(const float4* __restrict__ ego,
                                 const int*   __restrict__ off,
                                 const int*   __restrict__ cnt,
                                 const int2*  __restrict__ meta,
                                 float4*      __restrict__ X)
{
    int node = (blockIdx.x * blockDim.x + threadIdx.x) >> 5;
    int lane = threadIdx.x & 31;
    if (node >= NN) return;

    float4 hd = __ldg(ego + (size_t)node * 32 + lane);
    float4 a = hd;                               // self term (ego @ W1)
    float4 b = make_float4(0.f, 0.f, 0.f, 0.f);

    int e0 = __ldg(off + node);
    int n  = __ldg(cnt + node);

    #pragma unroll 4
    for (int t = 0; t < n; ++t) {
        int2 m = __ldg(meta + e0 + t);
        float w = __int_as_float(m.y);
        float4 hs = __ldg(ego + (size_t)m.x * 32 + lane);
        a.x = fmaf(w, hs.x, a.x);
        a.y = fmaf(w, hs.y, a.y);
        a.z = fmaf(w, hs.z, a.z);
        a.w = fmaf(w, hs.w, a.w);
        b.x = fmaf(w * hs.x, hd.x, b.x);
        b.y = fmaf(w * hs.y, hd.y, b.y);
        b.z = fmaf(w * hs.z, hd.z, b.z);
        b.w = fmaf(w * hs.w, hd.w, b.w);
    }

    X[(size_t)node * 64 + lane]      = a;
    X[(size_t)node * 64 + 32 + lane] = b;
}

// ---------------------------------------------------------------------------
// GEMM (f32x2 packed FMA) + leaky relu + row L2 normalize
// Block: 64 rows x 128 cols, 256 threads, thread tile 4 rows x 8 cols (4 col-pairs)
// ---------------------------------------------------------------------------
#define BM 64
#define XS_PITCH 65

__global__ void __launch_bounds__(256, 1)
gemm_epilogue_kernel(const float* __restrict__ W1,
                     const float* __restrict__ W2,
                     float*       __restrict__ out)
{
    extern __shared__ float smem[];
    float* Ws = smem;                 // 256*128 floats (128 KB)
    float* Xs = smem + KK * DD;       // [64 k][64 rows] pitch 65

    const int tid = threadIdx.x;
    const int tx  = tid & 15;
    const int ty  = tid >> 4;
    const int tx8 = tx * 8;
    const int ty4 = ty * 4;
    const int rowBase = blockIdx.x * BM;

    // Load W = [W1; W2] row-major [k][j]
    const float4* W1v = (const float4*)W1;
    const float4* W2v = (const float4*)W2;
    float4* Wsv = (float4*)Ws;
    #pragma unroll
    for (int i = 0; i < 32; ++i) {
        int m = tid + i * 256;
        int k  = m >> 5;
        int j4 = m & 31;
        Wsv[m] = (k < DD) ? W1v[(size_t)k * 32 + j4]
                          : W2v[(size_t)(k - DD) * 32 + j4];
    }

    unsigned long long acc2[4][4];    // [row][col-pair], each = 2 packed fp32
    #pragma unroll
    for (int i = 0; i < 4; ++i)
        #pragma unroll
        for (int j = 0; j < 4; ++j) acc2[i][j] = 0ull;

    const float4* X4 = (const float4*)g_X;
    __syncthreads();

    for (int kc = 0; kc < KK; kc += 64) {
        // Load X tile (64 rows x 64 k) transposed into Xs[k][row]
        #pragma unroll
        for (int i = 0; i < 4; ++i) {
            int l  = tid + i * 256;
            int r  = l >> 4;
            int kq = l & 15;
            int grow = rowBase + r;
            if (grow >= NN) grow = NN - 1;
            float4 v = X4[(size_t)grow * 64 + (kc >> 2) + kq];
            int kk = kq * 4;
            Xs[(kk + 0) * XS_PITCH + r] = v.x;
            Xs[(kk + 1) * XS_PITCH + r] = v.y;
            Xs[(kk + 2) * XS_PITCH + r] = v.z;
            Xs[(kk + 3) * XS_PITCH + r] = v.w;
        }
        __syncthreads();

        #pragma unroll 8
        for (int k = 0; k < 64; ++k) {
            unsigned long long xd[4];
            #pragma unroll
            for (int i = 0; i < 4; ++i) {
                float x = Xs[k * XS_PITCH + ty4 + i];
                asm("mov.b64 %0, {%1, %1};" : "=l"(xd[i]) : "f"(x));
            }
            const unsigned long long* wq =
                (const unsigned long long*)&Ws[(kc + k) * DD + tx8];
            unsigned long long w0 = wq[0], w1 = wq[1], w2 = wq[2], w3 = wq[3];
            #pragma unroll
            for (int i = 0; i < 4; ++i) {
                asm("fma.rn.f32x2 %0, %1, %2, %0;" : "+l"(acc2[i][0]) : "l"(xd[i]), "l"(w0));
                asm("fma.rn.f32x2 %0, %1, %2, %0;" : "+l"(acc2[i][1]) : "l"(xd[i]), "l"(w1));
                asm("fma.rn.f32x2 %0, %1, %2, %0;" : "+l"(acc2[i][2]) : "l"(xd[i]), "l"(w2));
                asm("fma.rn.f32x2 %0, %1, %2, %0;" : "+l"(acc2[i][3]) : "l"(xd[i]), "l"(w3));
            }
        }
        __syncthreads();
    }

    // Unpack, leaky relu, row L2 norm
    float acc[4][8];
    #pragma unroll
    for (int i = 0; i < 4; ++i)
        #pragma unroll
        for (int j = 0; j < 4; ++j) {
            unsigned int lo, hi;
            asm("mov.b64 {%0, %1}, %2;" : "=r"(lo), "=r"(hi) : "l"(acc2[i][j]));
            acc[i][2 * j]     = __uint_as_float(lo);
            acc[i][2 * j + 1] = __uint_as_float(hi);
        }

    float* red_ = Xs;
    #pragma unroll
    for (int i = 0; i < 4; ++i) {
        float p = 0.f;
        #pragma unroll
        for (int j = 0; j < 8; ++j) {
            float v = acc[i][j];
            v = (v >= 0.f) ? v : 0.2f * v;
            acc[i][j] = v;
            p = fmaf(v, v, p);
        }
        red_[(ty4 + i) * 16 + tx] = p;
    }
    __syncthreads();

    if (tid < BM) {
        float s = 0.f;
        #pragma unroll
        for (int t = 0; t < 16; ++t) s += red_[tid * 16 + t];
        red_[BM * 16 + tid] = 1.f / fmaxf(sqrtf(s), 1e-12f);
    }
    __syncthreads();

    float4* out4 = (float4*)out;
    #pragma unroll
    for (int i = 0; i < 4; ++i) {
        int grow = rowBase + ty4 + i;
        if (grow < NN) {
            float iv = red_[BM * 16 + ty4 + i];
            float4 o0 = make_float4(acc[i][0] * iv, acc[i][1] * iv,
                                    acc[i][2] * iv, acc[i][3] * iv);
            float4 o1 = make_float4(acc[i][4] * iv, acc[i][5] * iv,
                                    acc[i][6] * iv, acc[i][7] * iv);
            out4[(size_t)grow * 32 + tx * 2]     = o0;
            out4[(size_t)grow * 32 + tx * 2 + 1] = o1;
        }
    }
}

// ---------------------------------------------------------------------------
// Launch
// ---------------------------------------------------------------------------
extern "C" void kernel_launch(void* const* d_in, const int* in_sizes, int n_in,
                              void* d_out, int out_size)
{
    const float* ego  = (const float*)d_in[0];
    const float* norm = (const float*)d_in[1];
    const int*   src  = (const int*)d_in[2];
    const int*   dst  = (const int*)d_in[3];
    const float* W1   = (const float*)d_in[4];
    const float* W2   = (const float*)d_in[5];
    float* out = (float*)d_out;

    float* X;   cudaGetSymbolAddress((void**)&X,   g_X);
    int*   cnt; cudaGetSymbolAddress((void**)&cnt, g_cnt);
    int*   off; cudaGetSymbolAddress((void**)&off, g_off);
    int*   cur; cudaGetSymbolAddress((void**)&cur, g_cur);
    int*   part;cudaGetSymbolAddress((void**)&part,g_part);
    int2*  meta;cudaGetSymbolAddress((void**)&meta,g_meta);

    zero_cnt_kernel<<<(NN + 255) / 256, 256>>>(cnt);
    hist_kernel<<<(EE + 255) / 256, 256>>>(dst, cnt);
    scan_local_kernel<<<NB_SCAN, SCAN_CHUNK>>>(cnt, off, part);
    scan_part_kernel<<<1, 256>>>(part);
    scan_add_kernel<<<NB_SCAN, SCAN_CHUNK>>>(off, cur, part);
    scatter_kernel<<<(EE + 255) / 256, 256>>>(src, dst, norm, cur, meta);

    aggregate_kernel<<<(NN * 32 + 255) / 256, 256>>>(
        (const float4*)ego, off, cnt, meta, (float4*)X);

    int smem = (KK * DD + BM * XS_PITCH) * (int)sizeof(float);
    cudaFuncSetAttribute(gemm_epilogue_kernel,
                         cudaFuncAttributeMaxDynamicSharedMemorySize, smem);
    gemm_epilogue_kernel<<<(NN + BM - 1) / BM, 256, smem>>>(W1, W2, out);
}

// round 4
// speedup vs baseline: 1.8148x; 1.3744x over previous
#include <cuda_runtime.h>
#include <cuda_bf16.h>
#include <cstdint>
#include <math.h>

#define NN 100000
#define EE 1000000
#define DD 128
#define KK 256

#define BM 64
#define THREADS 512
#define NBLK ((NN + BM - 1) / BM)     // 1563

#define XS_PITCH 260                   // floats per row (256 + 4 pad)
#define WS_FLOATS (KK * DD)            // 32768
#define SMEM_FLOATS (WS_FLOATS + BM * XS_PITCH)

// Scratch
__device__ int  g_cnt[NN];
__device__ int  g_off[NN];
__device__ int  g_cur[NN];
__device__ int  g_total;
__device__ int2 g_meta[EE];            // {src, w_as_int}

// ---------------------------------------------------------------------------
// CSR build
// ---------------------------------------------------------------------------
__global__ void hist_kernel(const int* __restrict__ dst, int* __restrict__ cnt)
{
    int e = blockIdx.x * blockDim.x + threadIdx.x;
    if (e < EE) atomicAdd(&cnt[__ldg(dst + e)], 1);
}

__global__ void alloc_kernel(const int* __restrict__ cnt,
                             int* __restrict__ off,
                             int* __restrict__ cur,
                             int* __restrict__ total)
{
    int i = blockIdx.x * blockDim.x + threadIdx.x;
    if (i < NN) {
        int o = atomicAdd(total, cnt[i]);
        off[i] = o;
        cur[i] = o;
    }
}

__global__ void scatter_kernel(const int* __restrict__ src,
                               const int* __restrict__ dst,
                               const float* __restrict__ norm,
                               int* __restrict__ cur,
                               int2* __restrict__ meta)
{
    int e = blockIdx.x * blockDim.x + threadIdx.x;
    if (e >= EE) return;
    int s = __ldg(src + e);
    int d = __ldg(dst + e);
    float w = __ldg(norm + s) * __ldg(norm + d);
    int pos = atomicAdd(&cur[d], 1);
    meta[pos] = make_int2(s, __float_as_int(w));
}

// ---------------------------------------------------------------------------
// Fused: aggregate 64 nodes into SMEM, GEMM vs W=[W1;W2], leaky+L2norm, store.
// 512 threads: 16 warps. Aggregate: warp w -> nodes [base+4w, base+4w+4).
// GEMM: tx = tid&31 (4 cols), ty = tid>>5 (4 rows); acc in packed f32x2.
// ---------------------------------------------------------------------------
__device__ __forceinline__ void cp_async16(unsigned int dst, const void* src)
{
    asm volatile("cp.async.cg.shared.global [%0], [%1], 16;"
                 :: "r"(dst), "l"(src) : "memory");
}

__global__ void __launch_bounds__(THREADS, 1)
fused_kernel(const float4* __restrict__ ego,
             const int*   __restrict__ off,
             const int*   __restrict__ cnt,
             const int2*  __restrict__ meta,
             const float* __restrict__ W1,
             const float* __restrict__ W2,
             float*       __restrict__ out)
{
    extern __shared__ float smem[];
    float* Ws = smem;                   // [256][128]
    float* Xs = smem + WS_FLOATS;       // [64][260]

    const int tid  = threadIdx.x;
    const int lane = tid & 31;
    const int warp = tid >> 5;
    const int rowBase = blockIdx.x * BM;

    // ---- 1) issue async copy of W = [W1;W2] into SMEM (overlaps aggregate)
    {
        unsigned int wsBase;
        asm("{ .reg .u64 t; cvta.to.shared.u64 t, %1; cvt.u32.u64 %0, t; }"
            : "=r"(wsBase) : "l"(Ws));
        const float4* W1v = (const float4*)W1;
        const float4* W2v = (const float4*)W2;
        #pragma unroll
        for (int i = 0; i < 16; ++i) {
            int m  = tid + i * THREADS;     // 0..8191 (float4 idx)
            int k  = m >> 5;
            int j4 = m & 31;
            const void* src = (k < DD) ? (const void*)&W1v[(size_t)k * 32 + j4]
                                       : (const void*)&W2v[(size_t)(k - DD) * 32 + j4];
            cp_async16(wsBase + m * 16, src);
        }
        asm volatile("cp.async.commit_group;" ::: "memory");
    }

    // ---- 2) aggregate 4 nodes per warp into Xs
    #pragma unroll
    for (int q = 0; q < 4; ++q) {
        int node = rowBase + warp * 4 + q;
        bool valid = node < NN;

        float4 hd = valid ? __ldg(ego + (size_t)node * 32 + lane)
                          : make_float4(0.f, 0.f, 0.f, 0.f);
        float4 a = hd;                      // self term
        float4 b = make_float4(0.f, 0.f, 0.f, 0.f);

        int n  = valid ? __ldg(cnt + node) : 0;
        int e0 = valid ? __ldg(off + node) : 0;

        for (int c = 0; c < n; c += 32) {
            int lim = min(32, n - c);
            int2 mm = (lane < lim) ? __ldg(meta + e0 + c + lane)
                                   : make_int2(0, 0);
            int j = 0;
            for (; j + 4 <= lim; j += 4) {
                int   s0 = __shfl_sync(0xffffffffu, mm.x, j + 0);
                int   s1 = __shfl_sync(0xffffffffu, mm.x, j + 1);
                int   s2 = __shfl_sync(0xffffffffu, mm.x, j + 2);
                int   s3 = __shfl_sync(0xffffffffu, mm.x, j + 3);
                float w0 = __int_as_float(__shfl_sync(0xffffffffu, mm.y, j + 0));
                float w1 = __int_as_float(__shfl_sync(0xffffffffu, mm.y, j + 1));
                float w2 = __int_as_float(__shfl_sync(0xffffffffu, mm.y, j + 2));
                float w3 = __int_as_float(__shfl_sync(0xffffffffu, mm.y, j + 3));
                float4 h0 = __ldg(ego + (size_t)s0 * 32 + lane);
                float4 h1 = __ldg(ego + (size_t)s1 * 32 + lane);
                float4 h2 = __ldg(ego + (size_t)s2 * 32 + lane);
                float4 h3 = __ldg(ego + (size_t)s3 * 32 + lane);
                float t;
                t = w0 * h0.x; a.x += t; b.x = fmaf(t, hd.x, b.x);
                t = w0 * h0.y; a.y += t; b.y = fmaf(t, hd.y, b.y);
                t = w0 * h0.z; a.z += t; b.z = fmaf(t, hd.z, b.z);
                t = w0 * h0.w; a.w += t; b.w = fmaf(t, hd.w, b.w);
                t = w1 * h1.x; a.x += t; b.x = fmaf(t, hd.x, b.x);
                t = w1 * h1.y; a.y += t; b.y = fmaf(t, hd.y, b.y);
                t = w1 * h1.z; a.z += t; b.z = fmaf(t, hd.z, b.z);
                t = w1 * h1.w; a.w += t; b.w = fmaf(t, hd.w, b.w);
                t = w2 * h2.x; a.x += t; b.x = fmaf(t, hd.x, b.x);
                t = w2 * h2.y; a.y += t; b.y = fmaf(t, hd.y, b.y);
                t = w2 * h2.z; a.z += t; b.z = fmaf(t, hd.z, b.z);
                t = w2 * h2.w; a.w += t; b.w = fmaf(t, hd.w, b.w);
                t = w3 * h3.x; a.x += t; b.x = fmaf(t, hd.x, b.x);
                t = w3 * h3.y; a.y += t; b.y = fmaf(t, hd.y, b.y);
                t = w3 * h3.z; a.z += t; b.z = fmaf(t, hd.z, b.z);
                t = w3 * h3.w; a.w += t; b.w = fmaf(t, hd.w, b.w);
            }
            for (; j < lim; ++j) {
                int   s0 = __shfl_sync(0xffffffffu, mm.x, j);
                float w0 = __int_as_float(__shfl_sync(0xffffffffu, mm.y, j));
                float4 h0 = __ldg(ego + (size_t)s0 * 32 + lane);
                float t;
                t = w0 * h0.x; a.x += t; b.x = fmaf(t, hd.x, b.x);
                t = w0 * h0.y; a.y += t; b.y = fmaf(t, hd.y, b.y);
                t = w0 * h0.z; a.z += t; b.z = fmaf(t, hd.z, b.z);
                t = w0 * h0.w; a.w += t; b.w = fmaf(t, hd.w, b.w);
            }
        }

        int r = warp * 4 + q;
        *(float4*)&Xs[(size_t)r * XS_PITCH + lane * 4]       = a;
        *(float4*)&Xs[(size_t)r * XS_PITCH + DD + lane * 4]  = b;
    }

    asm volatile("cp.async.wait_group 0;" ::: "memory");
    __syncthreads();

    // ---- 3) GEMM: 64x128 tile, thread tile 4 rows x 4 cols (2 f32x2 pairs)
    const int tx  = tid & 31;        // col group: cols tx*4 .. tx*4+3
    const int ty  = tid >> 5;        // row group: rows ty*4 .. ty*4+3 (== warp)
    const int ty4 = ty * 4;
    const int tx4 = tx * 4;

    unsigned long long acc2[4][2];
    #pragma unroll
    for (int i = 0; i < 4; ++i) { acc2[i][0] = 0ull; acc2[i][1] = 0ull; }

    #pragma unroll 4
    for (int kb = 0; kb < KK; kb += 4) {
        float4 xr[4];
        #pragma unroll
        for (int i = 0; i < 4; ++i)
            xr[i] = *(const float4*)&Xs[(size_t)(ty4 + i) * XS_PITCH + kb];

        #pragma unroll
        for (int kk = 0; kk < 4; ++kk) {
            const unsigned long long* wq =
                (const unsigned long long*)&Ws[(size_t)(kb + kk) * DD + tx4];
            unsigned long long w0 = wq[0], w1 = wq[1];
            #pragma unroll
            for (int i = 0; i < 4; ++i) {
                float x = (kk == 0) ? xr[i].x : (kk == 1) ? xr[i].y
                        : (kk == 2) ? xr[i].z : xr[i].w;
                unsigned long long xd;
                asm("mov.b64 %0, {%1, %1};" : "=l"(xd) : "f"(x));
                asm("fma.rn.f32x2 %0, %1, %2, %0;" : "+l"(acc2[i][0]) : "l"(xd), "l"(w0));
                asm("fma.rn.f32x2 %0, %1, %2, %0;" : "+l"(acc2[i][1]) : "l"(xd), "l"(w1));
            }
        }
    }

    // ---- 4) epilogue: leaky relu, row L2 norm via warp butterfly, store
    float acc[4][4];
    float p[4];
    #pragma unroll
    for (int i = 0; i < 4; ++i) {
        unsigned int lo, hi;
        asm("mov.b64 {%0, %1}, %2;" : "=r"(lo), "=r"(hi) : "l"(acc2[i][0]));
        acc[i][0] = __uint_as_float(lo);
        acc[i][1] = __uint_as_float(hi);
        asm("mov.b64 {%0, %1}, %2;" : "=r"(lo), "=r"(hi) : "l"(acc2[i][1]));
        acc[i][2] = __uint_as_float(lo);
        acc[i][3] = __uint_as_float(hi);
        float s = 0.f;
        #pragma unroll
        for (int j = 0; j < 4; ++j) {
            float v = acc[i][j];
            v = (v >= 0.f) ? v : 0.2f * v;
            acc[i][j] = v;
            s = fmaf(v, v, s);
        }
        p[i] = s;
    }
    #pragma unroll
    for (int o = 16; o > 0; o >>= 1) {
        #pragma unroll
        for (int i = 0; i < 4; ++i)
            p[i] += __shfl_xor_sync(0xffffffffu, p[i], o);
    }

    float4* out4 = (float4*)out;
    #pragma unroll
    for (int i = 0; i < 4; ++i) {
        int grow = rowBase + ty4 + i;
        if (grow < NN) {
            float inv = 1.0f / fmaxf(sqrtf(p[i]), 1e-12f);
            out4[(size_t)grow * 32 + tx] =
                make_float4(acc[i][0] * inv, acc[i][1] * inv,
                            acc[i][2] * inv, acc[i][3] * inv);
        }
    }
}

// ---------------------------------------------------------------------------
// Launch
// ---------------------------------------------------------------------------
extern "C" void kernel_launch(void* const* d_in, const int* in_sizes, int n_in,
                              void* d_out, int out_size)
{
    const float* ego  = (const float*)d_in[0];
    const float* norm = (const float*)d_in[1];
    const int*   src  = (const int*)d_in[2];
    const int*   dst  = (const int*)d_in[3];
    const float* W1   = (const float*)d_in[4];
    const float* W2   = (const float*)d_in[5];
    float* out = (float*)d_out;

    int*  cnt;   cudaGetSymbolAddress((void**)&cnt,   g_cnt);
    int*  off;   cudaGetSymbolAddress((void**)&off,   g_off);
    int*  cur;   cudaGetSymbolAddress((void**)&cur,   g_cur);
    int*  total; cudaGetSymbolAddress((void**)&total, g_total);
    int2* meta;  cudaGetSymbolAddress((void**)&meta,  g_meta);

    cudaMemsetAsync(cnt, 0, NN * sizeof(int));
    cudaMemsetAsync(total, 0, sizeof(int));
    hist_kernel<<<(EE + 255) / 256, 256>>>(dst, cnt);
    alloc_kernel<<<(NN + 255) / 256, 256>>>(cnt, off, cur, total);
    scatter_kernel<<<(EE + 255) / 256, 256>>>(src, dst, norm, cur, meta);

    int smem = SMEM_FLOATS * (int)sizeof(float);   // ~193 KB
    cudaFuncSetAttribute(fused_kernel,
                         cudaFuncAttributeMaxDynamicSharedMemorySize, smem);
    fused_kernel<<<NBLK, THREADS, smem>>>(
        (const float4*)ego, off, cnt, meta, W1, W2, out);
}